// round 12
// baseline (speedup 1.0000x reference)
#include <cuda_runtime.h>
#include <cuda_bf16.h>
#include <stdint.h>

// Problem:
//   x:   (B, S) token ids in [0, V)   (B=512, S=1024, V=50257 per reference)
//   idf: (V,) fp32
//   out: (B, V) fp32 = (tf * idf) / rowsum(tf * idf)
//
// Algebra: rowsum(tf*idf) = sum_s idf[x[row, s]]  -> no histogram needed.
// Strategy: memset(out, 0) [103 MB, HBM-write bound, ~16 us floor] + one
// scatter kernel doing atomicAdd(out[row, tok], idf[tok] / n_row) (~5 us).

#define NTHREADS 256

__inline__ __device__ float warp_reduce_sum(float v) {
    #pragma unroll
    for (int o = 16; o > 0; o >>= 1)
        v += __shfl_xor_sync(0xffffffffu, v, o);
    return v;
}

__global__ __launch_bounds__(NTHREADS, 4)
void tfidf_scatter(const void* __restrict__ xv,
                   const float* __restrict__ idf,
                   float* __restrict__ out,
                   int seq, int vocab) {
    const int row = blockIdx.x;
    const int tid = threadIdx.x;

    // --- index-width autodetect (int64 vs int32 token buffer) ---
    // Little-endian int64 values < 2^31 have zero high words at odd 32-bit
    // indices. For int32 data those words are real tokens; P[all 4 == 0]
    // ~ (1/50257)^4 — negligible. Uniform branch across the whole grid.
    const int* xi = (const int*)xv;
    const bool is64 = (xi[1] == 0) & (xi[3] == 0) & (xi[5] == 0) & (xi[7] == 0);

    const long long* x64 = (const long long*)xv + (size_t)row * seq;
    const int*       x32 = xi + (size_t)row * seq;

    // Pass 1: gather idf weights and reduce the row normalizer.
    // idf table (200 KB) is L2-resident after first touch.
    float partial = 0.0f;
    for (int s = tid; s < seq; s += NTHREADS) {
        int tok = is64 ? (int)x64[s] : x32[s];
        partial += __ldg(idf + tok);
    }

    // block reduction: warp shuffle + smem across 8 warps
    __shared__ float red[NTHREADS / 32];
    __shared__ float inv_n_sh;
    float ws = warp_reduce_sum(partial);
    const int lane = tid & 31;
    const int warp = tid >> 5;
    if (lane == 0) red[warp] = ws;
    __syncthreads();
    if (warp == 0) {
        float v = (lane < (NTHREADS / 32)) ? red[lane] : 0.0f;
        v = warp_reduce_sum(v);
        if (lane == 0) inv_n_sh = 1.0f / v;
    }
    __syncthreads();
    const float inv_n = inv_n_sh;

    // Pass 2: scatter. Token words are L2/L1-hot from pass 1. Duplicates
    // within a row resolve via fp32 atomics (REDG-class, mostly distinct
    // addresses -> ~0.85 cyc/lane; no return value needed).
    float* orow = out + (size_t)row * vocab;
    for (int s = tid; s < seq; s += NTHREADS) {
        int tok = is64 ? (int)x64[s] : x32[s];
        atomicAdd(orow + tok, __ldg(idf + tok) * inv_n);
    }
}

extern "C" void kernel_launch(void* const* d_in, const int* in_sizes, int n_in,
                              void* d_out, int out_size) {
    (void)n_in;
    const void*  x   = d_in[0];                 // (B, S) tokens
    const float* idf = (const float*)d_in[1];   // (V,) fp32
    float*       out = (float*)d_out;           // (B, V) fp32

    const int vocab = in_sizes[1];              // V = idf element count
    const int batch = out_size / vocab;         // B = 512
    const int seq   = in_sizes[0] / batch;      // S = tokens per row (x is
                                                // reported in elements)

    // 1) zero the 103 MB output — single memset node, HBM-write bound
    cudaMemsetAsync(d_out, 0, (size_t)out_size * sizeof(float), 0);

    // 2) reduce + scatter, one block per row (stream-ordered after memset)
    tfidf_scatter<<<batch, NTHREADS, 0, 0>>>(x, idf, out, seq, vocab);
}